// round 15
// baseline (speedup 1.0000x reference)
#include <cuda_runtime.h>
#include <cuda_fp16.h>
#include <cstdint>

#define E_EDGES 500000
#define HN      256
#define NHALF   128
#define KDIM    512
#define TILE_M  128
#define KC      32
#define NCHUNKS (KDIM / KC)    // 16
#define THREADS 256

// ---------------- device-global scratch (compile-time, no runtime alloc) ----
__device__ __align__(16) __half g_W1_hi[KDIM * HN];   // [k][n]
__device__ float g_part0[E_EDGES];
__device__ float g_part1[E_EDGES];

// ---------------- prep: W1 fp32 -> fp16 --------------------------------------
__global__ void prep_w1_kernel(const float* __restrict__ W1) {
    int i = blockIdx.x * blockDim.x + threadIdx.x;
    if (i >= KDIM * HN) return;
    g_W1_hi[i] = __float2half_rn(W1[i]);
}

// ---------------- final: out = p0 + p1 + b2 ----------------------------------
__global__ void final_kernel(const float* __restrict__ b2, float* __restrict__ out) {
    int i = blockIdx.x * blockDim.x + threadIdx.x;
    if (i < E_EDGES) out[i] = g_part0[i] + g_part1[i] + b2[0];
}

// ---------------- PTX helpers ------------------------------------------------
__device__ __forceinline__ uint32_t smem_u32(const void* p) {
    uint32_t a;
    asm("{ .reg .u64 t; cvta.to.shared.u64 t, %1; cvt.u32.u64 %0, t; }" : "=r"(a) : "l"(p));
    return a;
}
__device__ __forceinline__ void ldsm_x4(uint32_t addr, uint32_t& r0, uint32_t& r1,
                                        uint32_t& r2, uint32_t& r3) {
    asm volatile("ldmatrix.sync.aligned.m8n8.x4.shared.b16 {%0,%1,%2,%3}, [%4];"
                 : "=r"(r0), "=r"(r1), "=r"(r2), "=r"(r3) : "r"(addr));
}
__device__ __forceinline__ void ldsm_x4_t(uint32_t addr, uint32_t& r0, uint32_t& r1,
                                          uint32_t& r2, uint32_t& r3) {
    asm volatile("ldmatrix.sync.aligned.m8n8.x4.trans.shared.b16 {%0,%1,%2,%3}, [%4];"
                 : "=r"(r0), "=r"(r1), "=r"(r2), "=r"(r3) : "r"(addr));
}
__device__ __forceinline__ void mma16816(float* c, const uint32_t* a, uint32_t b0, uint32_t b1) {
    asm volatile(
        "mma.sync.aligned.m16n8k16.row.col.f32.f16.f16.f32 "
        "{%0,%1,%2,%3}, {%4,%5,%6,%7}, {%8,%9}, {%0,%1,%2,%3};"
        : "+f"(c[0]), "+f"(c[1]), "+f"(c[2]), "+f"(c[3])
        : "r"(a[0]), "r"(a[1]), "r"(a[2]), "r"(a[3]), "r"(b0), "r"(b1));
}
__device__ __forceinline__ void cp_async16(uint32_t saddr, const void* gptr) {
    asm volatile("cp.async.cg.shared.global [%0], [%1], 16;" :: "r"(saddr), "l"(gptr));
}
#define CP_COMMIT() asm volatile("cp.async.commit_group;" ::: "memory")
#define CP_WAIT0()  asm volatile("cp.async.wait_group 0;"  ::: "memory")
#define CP_WAIT1()  asm volatile("cp.async.wait_group 1;"  ::: "memory")

// ---------------- smem layout ------------------------------------------------
// A: 2 stages x [128][32h] stride 80B = 2 x 10240
// B: 3 stages x [32][128h] stride 272B = 3 x 8704
#define A_STRIDE_B 80
#define A_STAGE_B  10240
#define B_STRIDE_B 272
#define B_STAGE_B  8704
#define SM_B       20480
#define SM_DYN_BYTES (SM_B + 3 * B_STAGE_B)   // 46592

__global__ __launch_bounds__(THREADS, 2)
void linkpred_hmma_kernel(const float* __restrict__ emb_src,
                          const float* __restrict__ emb_dst,
                          const int*   __restrict__ eidx,
                          const float* __restrict__ b1,
                          const float* __restrict__ W2)
{
    extern __shared__ char sm[];
    __shared__ float s_b1[NHALF], s_w2[NHALF];
    __shared__ float s_part[2][TILE_M];

    const int t    = threadIdx.x;
    const int lane = t & 31;
    const int wid  = t >> 5;
    const int wm   = wid & 3;    // 4 warps over M (32 rows each)
    const int wn   = wid >> 2;   // 2 warps over N (64 cols each)
    const int m0   = blockIdx.x * TILE_M;
    const int ny   = blockIdx.y;         // 0 or 1: which N-half
    const int nb   = ny * NHALF;         // global col base

    if (t < NHALF) { s_b1[t] = b1[nb + t]; s_w2[t] = W2[nb + t]; }

    // ---- A gather: 2 threads per edge row, 16 floats (64B) each
    const int arow = t >> 1;
    const int aseg = t & 1;
    int mg = m0 + arow;
    int mc = (mg < E_EDGES) ? mg : (E_EDGES - 1);
    const float* psrc = emb_src + (size_t)eidx[mc] * HN;
    const float* pdst = emb_dst + (size_t)eidx[E_EDGES + mc] * HN;

    // ---- B copy coords: thread -> (k-row, 16-half segment)
    const int bkrow = t >> 3;          // 0..31
    const int bnseg = (t & 7) * 16;    // halves within the 128-half slice

    const uint32_t smb = smem_u32(sm);

    // ldmatrix lane addressing
    const uint32_t a_lrow = (uint32_t)(wm * 32 + (lane & 15));
    const uint32_t a_lcol = (uint32_t)((lane >> 4) * 8);            // halves
    const uint32_t b_lrow = (uint32_t)(lane & 15);
    const uint32_t b_lcol = (uint32_t)(wn * 64 + (lane >> 4) * 8);  // halves

    // acc[f][g][c]: rows wm*32 + f*16, local cols wn*64 + g*8
    float acc[2][8][4];
    #pragma unroll
    for (int f = 0; f < 2; f++)
        #pragma unroll
        for (int g = 0; g < 8; g++)
            #pragma unroll
            for (int c = 0; c < 4; c++) acc[f][g][c] = 0.0f;

    float4 aR[4];

    auto a_issue = [&](int ch) {
        const int kbase = ch * KC;   // chunks 0-7: src, 8-15: dst
        const float* rp = ((kbase < HN) ? (psrc + kbase) : (pdst + (kbase - HN)))
                          + aseg * 16;
        aR[0] = __ldg((const float4*)(rp + 0));
        aR[1] = __ldg((const float4*)(rp + 4));
        aR[2] = __ldg((const float4*)(rp + 8));
        aR[3] = __ldg((const float4*)(rp + 12));
    };
    auto a_store = [&](int stageA) {
        float f[16] = {aR[0].x, aR[0].y, aR[0].z, aR[0].w,
                       aR[1].x, aR[1].y, aR[1].z, aR[1].w,
                       aR[2].x, aR[2].y, aR[2].z, aR[2].w,
                       aR[3].x, aR[3].y, aR[3].z, aR[3].w};
        alignas(16) __half hs[16];
        #pragma unroll
        for (int i = 0; i < 16; i++) hs[i] = __float2half_rn(f[i]);
        char* base = sm + stageA * A_STAGE_B;
        uint32_t off = (uint32_t)arow * A_STRIDE_B + aseg * 32;
        *(uint4*)(base + off)      = ((const uint4*)hs)[0];
        *(uint4*)(base + off + 16) = ((const uint4*)hs)[1];
    };
    auto b_issue = [&](int ch, int stageB) {
        const int kbase = ch * KC;
        const __half* gh = g_W1_hi + (size_t)(kbase + bkrow) * HN + nb + bnseg;
        uint32_t off = smb + SM_B + stageB * B_STAGE_B
                     + (uint32_t)bkrow * B_STRIDE_B + bnseg * 2;
        cp_async16(off,      gh);
        cp_async16(off + 16, gh + 8);
    };
    auto compute = [&](int stageA, int stageB) {
        const uint32_t abase = smb + stageA * A_STAGE_B;
        const uint32_t bbase = smb + SM_B + stageB * B_STAGE_B;
        #pragma unroll
        for (int ks = 0; ks < 2; ks++) {
            uint32_t ah[2][4];
            #pragma unroll
            for (int f = 0; f < 2; f++) {
                uint32_t aaddr = abase + (a_lrow + f * 16) * A_STRIDE_B
                               + (ks * 16 + a_lcol) * 2;
                ldsm_x4(aaddr, ah[f][0], ah[f][1], ah[f][2], ah[f][3]);
            }
            #pragma unroll
            for (int g4 = 0; g4 < 4; g4++) {
                uint32_t baddr = bbase + (ks * 16 + b_lrow) * B_STRIDE_B
                               + (b_lcol + g4 * 16) * 2;
                uint32_t b0, b1r, b2r, b3;
                ldsm_x4_t(baddr, b0, b1r, b2r, b3);
                #pragma unroll
                for (int f = 0; f < 2; f++) {
                    mma16816(acc[f][g4 * 2],     ah[f], b0,  b1r);
                    mma16816(acc[f][g4 * 2 + 1], ah[f], b2r, b3);
                }
            }
        }
    };

    // ---- prologue: A chunk0 -> stage0; B chunks 0,1 -> stages 0,1
    a_issue(0);
    b_issue(0, 0);
    CP_COMMIT();
    b_issue(1, 1);
    CP_COMMIT();
    a_store(0);
    CP_WAIT1();
    __syncthreads();

    // ---- mainloop: B 3-stage ring, A 2-stage, one sync per chunk
    #pragma unroll 1
    for (int ch = 0; ch < NCHUNKS; ch++) {
        const int aCur = ch & 1;
        const int bCur = ch % 3;
        if (ch + 1 < NCHUNKS) a_issue(ch + 1);
        if (ch + 2 < NCHUNKS) {
            b_issue(ch + 2, (ch + 2) % 3);
            CP_COMMIT();
        }
        compute(aCur, bCur);
        if (ch + 1 < NCHUNKS) {
            a_store(aCur ^ 1);
            if (ch + 2 < NCHUNKS) CP_WAIT1();
            else                  CP_WAIT0();
        }
        __syncthreads();
    }

    // ---- fused epilogue: relu(acc + b1) * W2 over this N-half ---------------
    #pragma unroll
    for (int f = 0; f < 2; f++) {
        float s0 = 0.0f, s1 = 0.0f;
        #pragma unroll
        for (int g = 0; g < 8; g++) {
            const int col = wn * 64 + g * 8 + (lane & 3) * 2;
            const float b1a = s_b1[col], b1b = s_b1[col + 1];
            const float w2a = s_w2[col], w2b = s_w2[col + 1];
            float v;
            v = acc[f][g][0] + b1a; v = fmaxf(v, 0.0f); s0 = fmaf(v, w2a, s0);
            v = acc[f][g][1] + b1b; v = fmaxf(v, 0.0f); s0 = fmaf(v, w2b, s0);
            v = acc[f][g][2] + b1a; v = fmaxf(v, 0.0f); s1 = fmaf(v, w2a, s1);
            v = acc[f][g][3] + b1b; v = fmaxf(v, 0.0f); s1 = fmaf(v, w2b, s1);
        }
        s0 += __shfl_xor_sync(0xffffffffu, s0, 1);
        s0 += __shfl_xor_sync(0xffffffffu, s0, 2);
        s1 += __shfl_xor_sync(0xffffffffu, s1, 1);
        s1 += __shfl_xor_sync(0xffffffffu, s1, 2);
        if ((lane & 3) == 0) {
            const int r = wm * 32 + f * 16 + (lane >> 2);
            s_part[wn][r]     = s0;
            s_part[wn][r + 8] = s1;
        }
    }
    __syncthreads();

    if (t < TILE_M) {
        const int mgo = m0 + t;
        if (mgo < E_EDGES) {
            float p = s_part[0][t] + s_part[1][t];
            if (ny == 0) g_part0[mgo] = p;
            else         g_part1[mgo] = p;
        }
    }
}

// ---------------- launch -----------------------------------------------------
extern "C" void kernel_launch(void* const* d_in, const int* in_sizes, int n_in,
                              void* d_out, int out_size) {
    const float* emb_src = (const float*)d_in[0];
    const float* emb_dst = (const float*)d_in[1];
    const int*   eidx    = (const int*)  d_in[2];
    const float* W1      = (const float*)d_in[3];
    const float* b1      = (const float*)d_in[4];
    const float* W2      = (const float*)d_in[5];
    const float* b2      = (const float*)d_in[6];
    float* out = (float*)d_out;

    static bool attr_done = false;
    if (!attr_done) {
        cudaFuncSetAttribute(linkpred_hmma_kernel,
                             cudaFuncAttributeMaxDynamicSharedMemorySize, SM_DYN_BYTES);
        attr_done = true;
    }

    prep_w1_kernel<<<(KDIM * HN + 255) / 256, 256>>>(W1);

    dim3 grid((E_EDGES + TILE_M - 1) / TILE_M, 2);   // 3907 x 2
    linkpred_hmma_kernel<<<grid, THREADS, SM_DYN_BYTES>>>(
        emb_src, emb_dst, eidx, b1, W2);

    final_kernel<<<(E_EDGES + 511) / 512, 512>>>(b2, out);
}

// round 16
// speedup vs baseline: 1.0404x; 1.0404x over previous
#include <cuda_runtime.h>
#include <cuda_fp16.h>
#include <cstdint>

#define E_EDGES 500000
#define HN      256
#define KDIM    512
#define TILE_M  64
#define KC      32
#define NCHUNKS (KDIM / KC)    // 16
#define THREADS 256

// ---------------- device-global scratch (compile-time, no runtime alloc) ----
__device__ __align__(16) __half g_W1_hi[KDIM * HN];   // [k][n]

// ---------------- prep: W1 fp32 -> fp16 --------------------------------------
__global__ void prep_w1_kernel(const float* __restrict__ W1) {
    int i = blockIdx.x * blockDim.x + threadIdx.x;
    if (i >= KDIM * HN) return;
    g_W1_hi[i] = __float2half_rn(W1[i]);
}

// ---------------- PTX helpers ------------------------------------------------
__device__ __forceinline__ uint32_t smem_u32(const void* p) {
    uint32_t a;
    asm("{ .reg .u64 t; cvta.to.shared.u64 t, %1; cvt.u32.u64 %0, t; }" : "=r"(a) : "l"(p));
    return a;
}
__device__ __forceinline__ void ldsm_x4(uint32_t addr, uint32_t& r0, uint32_t& r1,
                                        uint32_t& r2, uint32_t& r3) {
    asm volatile("ldmatrix.sync.aligned.m8n8.x4.shared.b16 {%0,%1,%2,%3}, [%4];"
                 : "=r"(r0), "=r"(r1), "=r"(r2), "=r"(r3) : "r"(addr));
}
__device__ __forceinline__ void ldsm_x4_t(uint32_t addr, uint32_t& r0, uint32_t& r1,
                                          uint32_t& r2, uint32_t& r3) {
    asm volatile("ldmatrix.sync.aligned.m8n8.x4.trans.shared.b16 {%0,%1,%2,%3}, [%4];"
                 : "=r"(r0), "=r"(r1), "=r"(r2), "=r"(r3) : "r"(addr));
}
__device__ __forceinline__ void mma16816(float* c, const uint32_t* a, uint32_t b0, uint32_t b1) {
    asm volatile(
        "mma.sync.aligned.m16n8k16.row.col.f32.f16.f16.f32 "
        "{%0,%1,%2,%3}, {%4,%5,%6,%7}, {%8,%9}, {%0,%1,%2,%3};"
        : "+f"(c[0]), "+f"(c[1]), "+f"(c[2]), "+f"(c[3])
        : "r"(a[0]), "r"(a[1]), "r"(a[2]), "r"(a[3]), "r"(b0), "r"(b1));
}
__device__ __forceinline__ void cp_async16(uint32_t saddr, const void* gptr) {
    asm volatile("cp.async.cg.shared.global [%0], [%1], 16;" :: "r"(saddr), "l"(gptr));
}
#define CP_COMMIT() asm volatile("cp.async.commit_group;" ::: "memory")
#define CP_WAIT0()  asm volatile("cp.async.wait_group 0;"  ::: "memory")
#define CP_WAIT1()  asm volatile("cp.async.wait_group 1;"  ::: "memory")

// ---------------- smem layout ------------------------------------------------
// A: 2 stages x [64][32h] stride 80B = 2 x 5120
// B: 3 stages x [32][256h] stride 528B = 3 x 16896
#define A_STRIDE_B 80
#define A_STAGE_B  5120
#define B_STRIDE_B 528
#define B_STAGE_B  16896
#define SM_B       10240
#define SM_DYN_BYTES (SM_B + 3 * B_STAGE_B)   // 60928

__global__ __launch_bounds__(THREADS, 2)
void linkpred_hmma_kernel(const float* __restrict__ emb_src,
                          const float* __restrict__ emb_dst,
                          const int*   __restrict__ eidx,
                          const float* __restrict__ b1,
                          const float* __restrict__ W2,
                          const float* __restrict__ b2,
                          float*       __restrict__ out)
{
    extern __shared__ char sm[];
    __shared__ float s_b1[HN], s_w2[HN];
    __shared__ float s_part[4][TILE_M];

    const int t    = threadIdx.x;
    const int lane = t & 31;
    const int wid  = t >> 5;
    const int wm   = wid & 1;    // 2 warps over M (32 rows each)
    const int wn   = wid >> 1;   // 4 warps over N (64 cols each)
    const int m0   = blockIdx.x * TILE_M;

    if (t < HN) { s_b1[t] = b1[t]; s_w2[t] = W2[t]; }

    // ---- A gather: 4 threads per edge row, 8 floats (32B) each
    const int arow = t >> 2;          // 0..63
    const int aseg = t & 3;           // 8-float segment
    int mg = m0 + arow;
    int mc = (mg < E_EDGES) ? mg : (E_EDGES - 1);
    const float* psrc = emb_src + (size_t)eidx[mc] * HN;
    const float* pdst = emb_dst + (size_t)eidx[E_EDGES + mc] * HN;

    // ---- B copy coords: thread -> (k-row, 32-half segment)
    const int bkrow = t >> 3;          // 0..31
    const int bnseg = (t & 7) * 32;    // halves

    const uint32_t smb = smem_u32(sm);

    // ldmatrix lane addressing
    const uint32_t a_lrow = (uint32_t)(wm * 32 + (lane & 15));
    const uint32_t a_lcol = (uint32_t)((lane >> 4) * 8);            // halves
    const uint32_t b_lrow = (uint32_t)(lane & 15);
    const uint32_t b_lcol = (uint32_t)(wn * 64 + (lane >> 4) * 8);  // halves

    // acc[f][g][c]: rows wm*32 + f*16, cols wn*64 + g*8
    float acc[2][8][4];
    #pragma unroll
    for (int f = 0; f < 2; f++)
        #pragma unroll
        for (int g = 0; g < 8; g++)
            #pragma unroll
            for (int c = 0; c < 4; c++) acc[f][g][c] = 0.0f;

    float4 aR[2];

    auto a_issue = [&](int ch) {
        const int kbase = ch * KC;   // chunks 0-7: src, 8-15: dst
        const float* rp = ((kbase < HN) ? (psrc + kbase) : (pdst + (kbase - HN)))
                          + aseg * 8;
        aR[0] = __ldg((const float4*)(rp + 0));
        aR[1] = __ldg((const float4*)(rp + 4));
    };
    auto a_store = [&](int stageA) {
        float f[8] = {aR[0].x, aR[0].y, aR[0].z, aR[0].w,
                      aR[1].x, aR[1].y, aR[1].z, aR[1].w};
        alignas(16) __half hs[8];
        #pragma unroll
        for (int i = 0; i < 8; i++) hs[i] = __float2half_rn(f[i]);
        char* base = sm + stageA * A_STAGE_B;
        uint32_t off = (uint32_t)arow * A_STRIDE_B + aseg * 16;
        *(uint4*)(base + off) = *((const uint4*)hs);
    };
    auto b_issue = [&](int ch, int stageB) {
        const int kbase = ch * KC;
        const __half* gh = g_W1_hi + (size_t)(kbase + bkrow) * HN + bnseg;
        uint32_t off = smb + SM_B + stageB * B_STAGE_B
                     + (uint32_t)bkrow * B_STRIDE_B + bnseg * 2;
        #pragma unroll
        for (int q = 0; q < 4; q++)
            cp_async16(off + q * 16, gh + 8 * q);
    };
    auto compute = [&](int stageA, int stageB) {
        const uint32_t abase = smb + stageA * A_STAGE_B;
        const uint32_t bbase = smb + SM_B + stageB * B_STAGE_B;
        #pragma unroll
        for (int ks = 0; ks < 2; ks++) {
            uint32_t ah[2][4];
            #pragma unroll
            for (int f = 0; f < 2; f++) {
                uint32_t aaddr = abase + (a_lrow + f * 16) * A_STRIDE_B
                               + (ks * 16 + a_lcol) * 2;
                ldsm_x4(aaddr, ah[f][0], ah[f][1], ah[f][2], ah[f][3]);
            }
            #pragma unroll
            for (int g4 = 0; g4 < 4; g4++) {
                uint32_t baddr = bbase + (ks * 16 + b_lrow) * B_STRIDE_B
                               + (b_lcol + g4 * 16) * 2;
                uint32_t b0, b1r, b2r, b3;
                ldsm_x4_t(baddr, b0, b1r, b2r, b3);
                #pragma unroll
                for (int f = 0; f < 2; f++) {
                    mma16816(acc[f][g4 * 2],     ah[f], b0,  b1r);
                    mma16816(acc[f][g4 * 2 + 1], ah[f], b2r, b3);
                }
            }
        }
    };

    // ---- prologue: A chunk0 -> stage0; B chunks 0,1 -> stages 0,1
    a_issue(0);
    b_issue(0, 0);
    CP_COMMIT();
    b_issue(1, 1);
    CP_COMMIT();
    a_store(0);
    CP_WAIT1();
    __syncthreads();

    // ---- mainloop: B 3-stage ring, A 2-stage, one sync per chunk
    #pragma unroll 1
    for (int ch = 0; ch < NCHUNKS; ch++) {
        const int aCur = ch & 1;
        const int bCur = ch % 3;
        if (ch + 1 < NCHUNKS) a_issue(ch + 1);
        if (ch + 2 < NCHUNKS) {
            b_issue(ch + 2, (ch + 2) % 3);
            CP_COMMIT();
        }
        compute(aCur, bCur);
        if (ch + 1 < NCHUNKS) {
            a_store(aCur ^ 1);
            if (ch + 2 < NCHUNKS) CP_WAIT1();
            else                  CP_WAIT0();
        }
        __syncthreads();
    }

    // ---- fused epilogue: relu(acc + b1) * W2 -> per-row partials ------------
    #pragma unroll
    for (int f = 0; f < 2; f++) {
        float s0 = 0.0f, s1 = 0.0f;
        #pragma unroll
        for (int g = 0; g < 8; g++) {
            const int col = wn * 64 + g * 8 + (lane & 3) * 2;
            const float b1a = s_b1[col], b1b = s_b1[col + 1];
            const float w2a = s_w2[col], w2b = s_w2[col + 1];
            float v;
            v = acc[f][g][0] + b1a; v = fmaxf(v, 0.0f); s0 = fmaf(v, w2a, s0);
            v = acc[f][g][1] + b1b; v = fmaxf(v, 0.0f); s0 = fmaf(v, w2b, s0);
            v = acc[f][g][2] + b1a; v = fmaxf(v, 0.0f); s1 = fmaf(v, w2a, s1);
            v = acc[f][g][3] + b1b; v = fmaxf(v, 0.0f); s1 = fmaf(v, w2b, s1);
        }
        s0 += __shfl_xor_sync(0xffffffffu, s0, 1);
        s0 += __shfl_xor_sync(0xffffffffu, s0, 2);
        s1 += __shfl_xor_sync(0xffffffffu, s1, 1);
        s1 += __shfl_xor_sync(0xffffffffu, s1, 2);
        if ((lane & 3) == 0) {
            const int r = wm * 32 + f * 16 + (lane >> 2);
            s_part[wn][r]     = s0;
            s_part[wn][r + 8] = s1;
        }
    }
    __syncthreads();

    if (t < TILE_M) {
        const int mgo = m0 + t;
        if (mgo < E_EDGES)
            out[mgo] = (s_part[0][t] + s_part[1][t])
                     + (s_part[2][t] + s_part[3][t]) + __ldg(b2);
    }
}

// ---------------- launch -----------------------------------------------------
extern "C" void kernel_launch(void* const* d_in, const int* in_sizes, int n_in,
                              void* d_out, int out_size) {
    const float* emb_src = (const float*)d_in[0];
    const float* emb_dst = (const float*)d_in[1];
    const int*   eidx    = (const int*)  d_in[2];
    const float* W1      = (const float*)d_in[3];
    const float* b1      = (const float*)d_in[4];
    const float* W2      = (const float*)d_in[5];
    const float* b2      = (const float*)d_in[6];
    float* out = (float*)d_out;

    static bool attr_done = false;
    if (!attr_done) {
        cudaFuncSetAttribute(linkpred_hmma_kernel,
                             cudaFuncAttributeMaxDynamicSharedMemorySize, SM_DYN_BYTES);
        attr_done = true;
    }

    prep_w1_kernel<<<(KDIM * HN + 255) / 256, 256>>>(W1);

    const int grid = (E_EDGES + TILE_M - 1) / TILE_M;   // 7813
    linkpred_hmma_kernel<<<grid, THREADS, SM_DYN_BYTES>>>(
        emb_src, emb_dst, eidx, b1, W2, b2, out);
}